// round 2
// baseline (speedup 1.0000x reference)
#include <cuda_runtime.h>
#include <float.h>

#define BB 4
#define NN 2048
#define MM 2048
#define DIN 3
#define HH 256
#define DD 64
#define KV 32
#define SPLITS 8
#define NSPLIT (NN / SPLITS)   /* 256 keys per split */
#define TK 16                  /* keys per shared tile */
#define QBLK 128               /* threads / queries per block */
#define BM (BB * MM)

// Scratch (static device arrays — no allocation).
__device__ float g_key[BB * NN * DD];                 // 2 MB
__device__ float g_query[BB * MM * DD];               // 2 MB
__device__ float g_part[SPLITS * (2 + KV) * BM];      // ~8.9 MB: [s][comp][gq]

// ---------------------------------------------------------------------------
// Stage 1: MLP embed. One thread computes 16 of the 64 output dims for one
// point (4 threads/point) so we get 256 blocks of parallelism. Hidden
// activations are recomputed 4x (cheap: 5 ops/j vs 16 FFMA/j).
// ---------------------------------------------------------------------------
__global__ __launch_bounds__(128) void embed_kernel(
    const float* __restrict__ coords,
    const float* __restrict__ W1, const float* __restrict__ b1,
    const float* __restrict__ W2, const float* __restrict__ b2,
    int which /* 0 = keys, 1 = queries */, int npts)
{
    __shared__ __align__(16) float W1s[DIN * HH];
    __shared__ float b1s[HH];
    __shared__ float b2s[DD];
    __shared__ __align__(16) float W2s[64 * DD];   // one 64-row hidden chunk

    float* outg = which ? g_query : g_key;

    const int tid = threadIdx.x;
    for (int i = tid; i < DIN * HH; i += QBLK) W1s[i] = W1[i];
    for (int i = tid; i < HH; i += QBLK)       b1s[i] = b1[i];
    for (int i = tid; i < DD; i += QBLK)       b2s[i] = b2[i];

    const int gt    = blockIdx.x * QBLK + tid;
    const int p     = gt >> 2;        // point index
    const int dpart = gt & 3;         // which 16-dim slice of the output
    const int d0    = dpart * 16;

    float c0 = 0.f, c1 = 0.f, c2 = 0.f;
    if (p < npts) {
        c0 = coords[p * 3 + 0];
        c1 = coords[p * 3 + 1];
        c2 = coords[p * 3 + 2];
    }

    float acc[16];
    #pragma unroll
    for (int d = 0; d < 16; d++) acc[d] = 0.f;

    for (int jc = 0; jc < HH; jc += 64) {
        __syncthreads();
        // stage W2 rows [jc, jc+64) — contiguous 64*DD floats
        {
            const float4* src = (const float4*)(W2 + (size_t)jc * DD);
            float4* dst = (float4*)W2s;
            #pragma unroll
            for (int i = tid; i < 64 * DD / 4; i += QBLK) dst[i] = src[i];
        }
        __syncthreads();
        #pragma unroll 4
        for (int j = 0; j < 64; j++) {
            const int jj = jc + j;
            float h = fmaxf(c0 * W1s[jj] + c1 * W1s[HH + jj] +
                            c2 * W1s[2 * HH + jj] + b1s[jj], 0.f);
            const float4* w2row = (const float4*)(W2s + j * DD + d0);
            #pragma unroll
            for (int q4 = 0; q4 < 4; q4++) {
                float4 w = w2row[q4];
                acc[4 * q4 + 0] += h * w.x;
                acc[4 * q4 + 1] += h * w.y;
                acc[4 * q4 + 2] += h * w.z;
                acc[4 * q4 + 3] += h * w.w;
            }
        }
    }

    if (p < npts) {
        float4* o = (float4*)(outg + (size_t)p * DD + d0);
        #pragma unroll
        for (int q4 = 0; q4 < 4; q4++) {
            float4 r;
            r.x = acc[4 * q4 + 0] + b2s[d0 + 4 * q4 + 0];
            r.y = acc[4 * q4 + 1] + b2s[d0 + 4 * q4 + 1];
            r.z = acc[4 * q4 + 2] + b2s[d0 + 4 * q4 + 2];
            r.w = acc[4 * q4 + 3] + b2s[d0 + 4 * q4 + 3];
            o[q4] = r;
        }
    }
}

// ---------------------------------------------------------------------------
// Stage 2: fused L1-cdist + online softmax + PV, split over the key axis.
// One thread = one query; query embedding (64 fp32) + acc[32] in registers.
// Keys/values stream through shared memory (broadcast LDS).
// ---------------------------------------------------------------------------
__global__ __launch_bounds__(QBLK, 3) void attn_partial_kernel(
    const float* __restrict__ values)
{
    __shared__ __align__(16) float ks[TK * DD];   // 4 KB
    __shared__ __align__(16) float vs[TK * KV];   // 2 KB

    const int tid   = threadIdx.x;
    const int b     = blockIdx.y;
    const int m     = blockIdx.x * QBLK + tid;
    const int split = blockIdx.z;
    const int gq    = b * MM + m;

    // query into registers
    float q[DD];
    {
        const float4* qp = (const float4*)(g_query + (size_t)gq * DD);
        #pragma unroll
        for (int i = 0; i < DD / 4; i++) {
            float4 v4 = qp[i];
            q[4 * i + 0] = v4.x; q[4 * i + 1] = v4.y;
            q[4 * i + 2] = v4.z; q[4 * i + 3] = v4.w;
        }
    }

    float mval = -FLT_MAX;
    float ssum = 0.f;
    float acc[KV];
    #pragma unroll
    for (int k = 0; k < KV; k++) acc[k] = 0.f;

    const int    n0      = split * NSPLIT;
    const float* keyBase = g_key  + (size_t)b * NN * DD;
    const float* valBase = values + (size_t)b * NN * KV;

    for (int t = 0; t < NSPLIT; t += TK) {
        __syncthreads();
        {   // cooperative stage of TK keys + values (both contiguous)
            const float4* src = (const float4*)(keyBase + (size_t)(n0 + t) * DD);
            float4* dst = (float4*)ks;
            #pragma unroll
            for (int i = tid; i < TK * DD / 4; i += QBLK) dst[i] = src[i];
            const float4* srcv = (const float4*)(valBase + (size_t)(n0 + t) * KV);
            float4* dstv = (float4*)vs;
            #pragma unroll
            for (int i = tid; i < TK * KV / 4; i += QBLK) dstv[i] = srcv[i];
        }
        __syncthreads();

        #pragma unroll 1
        for (int kk = 0; kk < TK; kk++) {
            const float* krow = ks + kk * DD;
            float s0 = 0.f, s1 = 0.f, s2 = 0.f, s3 = 0.f;
            #pragma unroll
            for (int d = 0; d < DD; d += 8) {
                float4 a  = *(const float4*)(krow + d);
                float4 c  = *(const float4*)(krow + d + 4);
                s0 += fabsf(a.x - q[d + 0]) + fabsf(a.y - q[d + 1]);
                s1 += fabsf(a.z - q[d + 2]) + fabsf(a.w - q[d + 3]);
                s2 += fabsf(c.x - q[d + 4]) + fabsf(c.y - q[d + 5]);
                s3 += fabsf(c.z - q[d + 6]) + fabsf(c.w - q[d + 7]);
            }
            float s  = (s0 + s1) + (s2 + s3);
            float lg = -0.5f * s * s;

            const float4* vrow = (const float4*)(vs + kk * KV);
            if (lg > mval) {
                float corr = __expf(mval - lg);
                mval = lg;
                ssum = ssum * corr + 1.f;
                #pragma unroll
                for (int k4 = 0; k4 < KV / 4; k4++) {
                    float4 v4 = vrow[k4];
                    acc[4 * k4 + 0] = acc[4 * k4 + 0] * corr + v4.x;
                    acc[4 * k4 + 1] = acc[4 * k4 + 1] * corr + v4.y;
                    acc[4 * k4 + 2] = acc[4 * k4 + 2] * corr + v4.z;
                    acc[4 * k4 + 3] = acc[4 * k4 + 3] * corr + v4.w;
                }
            } else {
                float p = __expf(lg - mval);
                ssum += p;
                #pragma unroll
                for (int k4 = 0; k4 < KV / 4; k4++) {
                    float4 v4 = vrow[k4];
                    acc[4 * k4 + 0] += p * v4.x;
                    acc[4 * k4 + 1] += p * v4.y;
                    acc[4 * k4 + 2] += p * v4.z;
                    acc[4 * k4 + 3] += p * v4.w;
                }
            }
        }
    }

    // write partial: layout [split][component][gq] for coalesced access
    float* base = g_part + (size_t)split * (2 + KV) * BM + gq;
    base[0]           = mval;
    base[(size_t)BM]  = ssum;
    #pragma unroll
    for (int k = 0; k < KV; k++)
        base[(size_t)(2 + k) * BM] = acc[k];
}

// ---------------------------------------------------------------------------
// Stage 3: merge the SPLITS partials per query and normalize.
// ---------------------------------------------------------------------------
__global__ __launch_bounds__(256) void merge_kernel(float* __restrict__ out)
{
    const int gq = blockIdx.x * blockDim.x + threadIdx.x;
    if (gq >= BM) return;

    float mx = -FLT_MAX;
    #pragma unroll
    for (int s = 0; s < SPLITS; s++)
        mx = fmaxf(mx, g_part[(size_t)s * (2 + KV) * BM + gq]);

    float tot = 0.f;
    float acc[KV];
    #pragma unroll
    for (int k = 0; k < KV; k++) acc[k] = 0.f;

    #pragma unroll
    for (int s = 0; s < SPLITS; s++) {
        const float* base = g_part + (size_t)s * (2 + KV) * BM + gq;
        float w = __expf(base[0] - mx);
        tot += base[(size_t)BM] * w;
        #pragma unroll
        for (int k = 0; k < KV; k++)
            acc[k] += base[(size_t)(2 + k) * BM] * w;
    }

    float inv = 1.f / tot;
    float* o = out + (size_t)gq * KV;
    #pragma unroll
    for (int k = 0; k < KV; k++) o[k] = acc[k] * inv;
}

// ---------------------------------------------------------------------------
extern "C" void kernel_launch(void* const* d_in, const int* in_sizes, int n_in,
                              void* d_out, int out_size)
{
    const float* coords_f = (const float*)d_in[0];
    const float* values_f = (const float*)d_in[1];
    const float* coords_t = (const float*)d_in[2];
    const float* Wk1 = (const float*)d_in[3];
    const float* bk1 = (const float*)d_in[4];
    const float* Wk2 = (const float*)d_in[5];
    const float* bk2 = (const float*)d_in[6];
    const float* Wq1 = (const float*)d_in[7];
    const float* bq1 = (const float*)d_in[8];
    const float* Wq2 = (const float*)d_in[9];
    const float* bq2 = (const float*)d_in[10];
    float* out = (float*)d_out;

    // Stage 1: embed keys and queries (4 threads per point, 16 dims each)
    {
        int npts = BB * NN;                      // 8192
        int blocks = (npts * 4) / QBLK;          // 256
        embed_kernel<<<blocks, QBLK>>>(coords_f, Wk1, bk1, Wk2, bk2, 0, npts);
        embed_kernel<<<blocks, QBLK>>>(coords_t, Wq1, bq1, Wq2, bq2, 1, npts);
    }

    // Stage 2: fused cdist + online-softmax + PV partials, split over keys
    {
        dim3 grid(MM / QBLK, BB, SPLITS);        // (16, 4, 8) = 512 blocks
        attn_partial_kernel<<<grid, QBLK>>>(values_f);
    }

    // Stage 3: merge partials
    merge_kernel<<<(BM + 255) / 256, 256>>>(out);
}

// round 3
// speedup vs baseline: 1.0751x; 1.0751x over previous
#include <cuda_runtime.h>
#include <float.h>

#define BB 4
#define NN 2048
#define MM 2048
#define DIN 3
#define HH 256
#define DD 64
#define KV 32
#define SPLITS 32
#define NSPLIT (NN / SPLITS)   /* 64 keys per split */
#define TK 8                   /* keys per shared tile */
#define QBLK 128               /* threads / queries per block */
#define BM (BB * MM)
#define NCOMP (2 + KV)         /* 34 partial components */

typedef unsigned long long u64;
#define ABS2MASK 0x7FFFFFFF7FFFFFFFULL
#define NLOG2E_HALF (-0.7213475204444817f)   /* -0.5 * log2(e) */

__device__ __forceinline__ u64 add2_(u64 a, u64 b) {
    u64 r; asm("add.rn.f32x2 %0,%1,%2;" : "=l"(r) : "l"(a), "l"(b)); return r;
}
__device__ __forceinline__ u64 mul2_(u64 a, u64 b) {
    u64 r; asm("mul.rn.f32x2 %0,%1,%2;" : "=l"(r) : "l"(a), "l"(b)); return r;
}
__device__ __forceinline__ u64 fma2_(u64 a, u64 b, u64 c) {
    u64 r; asm("fma.rn.f32x2 %0,%1,%2,%3;" : "=l"(r) : "l"(a), "l"(b), "l"(c)); return r;
}
__device__ __forceinline__ float ex2_(float x) {
    float r; asm("ex2.approx.f32 %0,%1;" : "=f"(r) : "f"(x)); return r;
}
__device__ __forceinline__ u64 pack2_(float lo, float hi) {
    u64 r; asm("mov.b64 %0,{%1,%2};" : "=l"(r) : "f"(lo), "f"(hi)); return r;
}
__device__ __forceinline__ void unpack2_(u64 v, float& lo, float& hi) {
    asm("mov.b64 {%0,%1},%2;" : "=f"(lo), "=f"(hi) : "l"(v));
}

// Scratch (static device arrays — no allocation).
__device__ float g_key[BB * NN * DD];                 // 2 MB
__device__ float g_query[BB * MM * DD];               // 2 MB
__device__ float g_part[SPLITS * NCOMP * BM];         // ~35.7 MB [s][comp][gq]

// ---------------------------------------------------------------------------
// Stage 1: MLP embed (unchanged structure). 4 threads/point, 16 dims each.
// ---------------------------------------------------------------------------
__global__ __launch_bounds__(128) void embed_kernel(
    const float* __restrict__ coords,
    const float* __restrict__ W1, const float* __restrict__ b1,
    const float* __restrict__ W2, const float* __restrict__ b2,
    int which, int npts)
{
    __shared__ __align__(16) float W1s[DIN * HH];
    __shared__ float b1s[HH];
    __shared__ float b2s[DD];
    __shared__ __align__(16) float W2s[64 * DD];

    float* outg = which ? g_query : g_key;

    const int tid = threadIdx.x;
    for (int i = tid; i < DIN * HH; i += QBLK) W1s[i] = W1[i];
    for (int i = tid; i < HH; i += QBLK)       b1s[i] = b1[i];
    for (int i = tid; i < DD; i += QBLK)       b2s[i] = b2[i];

    const int gt    = blockIdx.x * QBLK + tid;
    const int p     = gt >> 2;
    const int dpart = gt & 3;
    const int d0    = dpart * 16;

    float c0 = 0.f, c1 = 0.f, c2 = 0.f;
    if (p < npts) {
        c0 = coords[p * 3 + 0];
        c1 = coords[p * 3 + 1];
        c2 = coords[p * 3 + 2];
    }

    float acc[16];
    #pragma unroll
    for (int d = 0; d < 16; d++) acc[d] = 0.f;

    for (int jc = 0; jc < HH; jc += 64) {
        __syncthreads();
        {
            const float4* src = (const float4*)(W2 + (size_t)jc * DD);
            float4* dst = (float4*)W2s;
            for (int i = tid; i < 64 * DD / 4; i += QBLK) dst[i] = src[i];
        }
        __syncthreads();
        #pragma unroll 4
        for (int j = 0; j < 64; j++) {
            const int jj = jc + j;
            float h = fmaxf(c0 * W1s[jj] + c1 * W1s[HH + jj] +
                            c2 * W1s[2 * HH + jj] + b1s[jj], 0.f);
            const float4* w2row = (const float4*)(W2s + j * DD + d0);
            #pragma unroll
            for (int q4 = 0; q4 < 4; q4++) {
                float4 w = w2row[q4];
                acc[4 * q4 + 0] += h * w.x;
                acc[4 * q4 + 1] += h * w.y;
                acc[4 * q4 + 2] += h * w.z;
                acc[4 * q4 + 3] += h * w.w;
            }
        }
    }

    if (p < npts) {
        float4* o = (float4*)(outg + (size_t)p * DD + d0);
        #pragma unroll
        for (int q4 = 0; q4 < 4; q4++) {
            float4 r;
            r.x = acc[4 * q4 + 0] + b2s[d0 + 4 * q4 + 0];
            r.y = acc[4 * q4 + 1] + b2s[d0 + 4 * q4 + 1];
            r.z = acc[4 * q4 + 2] + b2s[d0 + 4 * q4 + 2];
            r.w = acc[4 * q4 + 3] + b2s[d0 + 4 * q4 + 3];
            o[q4] = r;
        }
    }
}

// ---------------------------------------------------------------------------
// Stage 2: fused L1-cdist + tile-deferred online softmax + PV.
// f32x2 packed math; base-2 logits; double-buffered smem tiles (1 bar/tile).
// ---------------------------------------------------------------------------
__global__ __launch_bounds__(QBLK, 3) void attn_partial_kernel(
    const float* __restrict__ values)
{
    __shared__ __align__(16) float ks[2][TK * DD];   // 2 x 2 KB
    __shared__ __align__(16) float vs[2][TK * KV];   // 2 x 1 KB

    const int tid   = threadIdx.x;
    const int b     = blockIdx.y;
    const int m     = blockIdx.x * QBLK + tid;
    const int split = blockIdx.z;
    const int gq    = b * MM + m;

    // negated query, packed f32x2 (so L1 subtract is a single packed add)
    u64 nq[DD / 2];
    {
        const float4* qp = (const float4*)(g_query + (size_t)gq * DD);
        #pragma unroll
        for (int i = 0; i < DD / 4; i++) {
            float4 v4 = qp[i];
            nq[2 * i + 0] = pack2_(-v4.x, -v4.y);
            nq[2 * i + 1] = pack2_(-v4.z, -v4.w);
        }
    }

    float mval = -FLT_MAX;
    float ssum = 0.f;
    u64 acc[KV / 2];
    #pragma unroll
    for (int j = 0; j < KV / 2; j++) acc[j] = 0ULL;

    const int    n0      = split * NSPLIT;
    const float* keyBase = g_key  + (size_t)b * NN * DD + (size_t)n0 * DD;
    const float* valBase = values + (size_t)b * NN * KV + (size_t)n0 * KV;

    // preload tile 0
    ((float4*)ks[0])[tid] = ((const float4*)keyBase)[tid];           // 128 float4
    if (tid < TK * KV / 4)
        ((float4*)vs[0])[tid] = ((const float4*)valBase)[tid];       // 64 float4
    __syncthreads();

    const int NT = NSPLIT / TK;   // 8 tiles
    for (int t = 0; t < NT; t++) {
        const int cur = t & 1;
        if (t + 1 < NT) {   // prefetch next tile into the other buffer
            ((float4*)ks[cur ^ 1])[tid] =
                ((const float4*)(keyBase + (size_t)(t + 1) * TK * DD))[tid];
            if (tid < TK * KV / 4)
                ((float4*)vs[cur ^ 1])[tid] =
                    ((const float4*)(valBase + (size_t)(t + 1) * TK * KV))[tid];
        }

        // ---- pass A: L1 distances -> base-2 logits for TK keys ----
        float lg[TK];
        float tm = -FLT_MAX;
        #pragma unroll
        for (int kk = 0; kk < TK; kk++) {
            const ulonglong2* kp = (const ulonglong2*)(ks[cur] + kk * DD);
            u64 sA = 0ULL, sB = 0ULL;
            #pragma unroll
            for (int i = 0; i < DD / 4; i++) {
                ulonglong2 k2 = kp[i];
                sA = add2_(sA, add2_(k2.x, nq[2 * i + 0]) & ABS2MASK);
                sB = add2_(sB, add2_(k2.y, nq[2 * i + 1]) & ABS2MASK);
            }
            float l0, h0;
            unpack2_(add2_(sA, sB), l0, h0);
            float s = l0 + h0;
            float lgv = (NLOG2E_HALF * s) * s;
            lg[kk] = lgv;
            tm = fmaxf(tm, lgv);
        }

        // ---- tile-level branchless rescale ----
        float newm = fmaxf(mval, tm);
        float corr = ex2_(mval - newm);     // -FLT_MAX - finite -> ex2 -> 0
        mval = newm;
        ssum *= corr;
        u64 corrp = pack2_(corr, corr);
        #pragma unroll
        for (int j = 0; j < KV / 2; j++) acc[j] = mul2_(acc[j], corrp);

        // ---- pass B: weights + PV (packed FFMA2) ----
        #pragma unroll
        for (int kk = 0; kk < TK; kk++) {
            float p = ex2_(lg[kk] - mval);
            ssum += p;
            u64 pp = pack2_(p, p);
            const ulonglong2* vp = (const ulonglong2*)(vs[cur] + kk * KV);
            #pragma unroll
            for (int j = 0; j < KV / 4; j++) {
                ulonglong2 v2 = vp[j];
                acc[2 * j + 0] = fma2_(v2.x, pp, acc[2 * j + 0]);
                acc[2 * j + 1] = fma2_(v2.y, pp, acc[2 * j + 1]);
            }
        }
        __syncthreads();
    }

    // write partial: [split][comp][gq], coalesced across tid
    float* base = g_part + (size_t)split * NCOMP * BM + gq;
    base[0]          = mval;
    base[(size_t)BM] = ssum;
    #pragma unroll
    for (int j = 0; j < KV / 2; j++) {
        float lo, hi;
        unpack2_(acc[j], lo, hi);
        base[(size_t)(2 + 2 * j + 0) * BM] = lo;
        base[(size_t)(2 + 2 * j + 1) * BM] = hi;
    }
}

// ---------------------------------------------------------------------------
// Stage 3: merge. One thread per (query, 4 value dims) -> 65536 threads.
// ---------------------------------------------------------------------------
__global__ __launch_bounds__(256) void merge_kernel(float* __restrict__ out)
{
    const int idx  = blockIdx.x * 256 + threadIdx.x;   // < BM * 8
    const int gq   = idx >> 3;
    const int quad = idx & 7;

    float mx = -FLT_MAX;
    #pragma unroll
    for (int s = 0; s < SPLITS; s++)
        mx = fmaxf(mx, g_part[(size_t)s * NCOMP * BM + gq]);

    float tot = 0.f;
    float a0 = 0.f, a1 = 0.f, a2 = 0.f, a3 = 0.f;
    #pragma unroll
    for (int s = 0; s < SPLITS; s++) {
        const float* base = g_part + (size_t)s * NCOMP * BM + gq;
        float w = ex2_(base[0] - mx);
        tot += base[(size_t)BM] * w;
        const float* ab = base + (size_t)(2 + 4 * quad) * BM;
        a0 += ab[0]              * w;
        a1 += ab[(size_t)BM]     * w;
        a2 += ab[(size_t)2 * BM] * w;
        a3 += ab[(size_t)3 * BM] * w;
    }

    float inv = 1.f / tot;   // tot >= 1: argmax key contributes weight 2^0
    float4 r = make_float4(a0 * inv, a1 * inv, a2 * inv, a3 * inv);
    *(float4*)(out + (size_t)gq * KV + 4 * quad) = r;
}

// ---------------------------------------------------------------------------
extern "C" void kernel_launch(void* const* d_in, const int* in_sizes, int n_in,
                              void* d_out, int out_size)
{
    const float* coords_f = (const float*)d_in[0];
    const float* values_f = (const float*)d_in[1];
    const float* coords_t = (const float*)d_in[2];
    const float* Wk1 = (const float*)d_in[3];
    const float* bk1 = (const float*)d_in[4];
    const float* Wk2 = (const float*)d_in[5];
    const float* bk2 = (const float*)d_in[6];
    const float* Wq1 = (const float*)d_in[7];
    const float* bq1 = (const float*)d_in[8];
    const float* Wq2 = (const float*)d_in[9];
    const float* bq2 = (const float*)d_in[10];
    float* out = (float*)d_out;

    {
        int npts = BB * NN;                       // 8192
        int blocks = (npts * 4) / QBLK;           // 256
        embed_kernel<<<blocks, QBLK>>>(coords_f, Wk1, bk1, Wk2, bk2, 0, npts);
        embed_kernel<<<blocks, QBLK>>>(coords_t, Wq1, bq1, Wq2, bq2, 1, npts);
    }

    {
        dim3 grid(MM / QBLK, BB, SPLITS);         // (16, 4, 32) = 2048 blocks
        attn_partial_kernel<<<grid, QBLK>>>(values_f);
    }

    merge_kernel<<<(BM * 8) / 256, 256>>>(out);
}

// round 4
// speedup vs baseline: 1.1664x; 1.0849x over previous
#include <cuda_runtime.h>
#include <float.h>

#define BB 4
#define NN 2048
#define MM 2048
#define DIN 3
#define HH 256
#define DD 64
#define KV 32
#define SPLITS 32
#define NSPLIT (NN / SPLITS)   /* 64 keys per split */
#define TK 8                   /* keys per shared tile */
#define QBLK 128               /* threads / queries per block */
#define BM (BB * MM)
#define NCOMP (2 + KV)         /* 34 partial components */

typedef unsigned long long u64;
#define NLOG2E_HALF (-0.7213475204444817f)   /* -0.5 * log2(e) */

__device__ __forceinline__ u64 mul2_(u64 a, u64 b) {
    u64 r; asm("mul.rn.f32x2 %0,%1,%2;" : "=l"(r) : "l"(a), "l"(b)); return r;
}
__device__ __forceinline__ u64 fma2_(u64 a, u64 b, u64 c) {
    u64 r; asm("fma.rn.f32x2 %0,%1,%2,%3;" : "=l"(r) : "l"(a), "l"(b), "l"(c)); return r;
}
__device__ __forceinline__ float ex2_(float x) {
    float r; asm("ex2.approx.f32 %0,%1;" : "=f"(r) : "f"(x)); return r;
}
__device__ __forceinline__ u64 pack2_(float lo, float hi) {
    u64 r; asm("mov.b64 %0,{%1,%2};" : "=l"(r) : "f"(lo), "f"(hi)); return r;
}
__device__ __forceinline__ void unpack2_(u64 v, float& lo, float& hi) {
    asm("mov.b64 {%0,%1},%2;" : "=f"(lo), "=f"(hi) : "l"(v));
}

// Scratch (static device arrays — no allocation).
__device__ float g_key[BB * NN * DD];                 // 2 MB
__device__ float g_query[BB * MM * DD];               // 2 MB
__device__ float g_ksum[BB * NN];                     // per-key  sum of dims
__device__ float g_qsum[BB * MM];                     // per-query sum of dims
__device__ float g_part[SPLITS * NCOMP * BM];         // ~35.7 MB [s][comp][gq]

// ---------------------------------------------------------------------------
// Stage 1: MLP embed. 4 threads/point, 16 dims each. Epilogue also produces
// the per-point coordinate-sum (shfl-reduce over the 4 sibling lanes) needed
// by the min-sum L1 identity.
// ---------------------------------------------------------------------------
__global__ __launch_bounds__(128) void embed_kernel(
    const float* __restrict__ coords,
    const float* __restrict__ W1, const float* __restrict__ b1,
    const float* __restrict__ W2, const float* __restrict__ b2,
    int which, int npts)
{
    __shared__ __align__(16) float W1s[DIN * HH];
    __shared__ float b1s[HH];
    __shared__ float b2s[DD];
    __shared__ __align__(16) float W2s[64 * DD];

    float* outg = which ? g_query : g_key;
    float* sumg = which ? g_qsum  : g_ksum;

    const int tid = threadIdx.x;
    for (int i = tid; i < DIN * HH; i += QBLK) W1s[i] = W1[i];
    for (int i = tid; i < HH; i += QBLK)       b1s[i] = b1[i];
    for (int i = tid; i < DD; i += QBLK)       b2s[i] = b2[i];

    const int gt    = blockIdx.x * QBLK + tid;
    const int p     = gt >> 2;
    const int dpart = gt & 3;
    const int d0    = dpart * 16;

    float c0 = 0.f, c1 = 0.f, c2 = 0.f;
    if (p < npts) {
        c0 = coords[p * 3 + 0];
        c1 = coords[p * 3 + 1];
        c2 = coords[p * 3 + 2];
    }

    float acc[16];
    #pragma unroll
    for (int d = 0; d < 16; d++) acc[d] = 0.f;

    for (int jc = 0; jc < HH; jc += 64) {
        __syncthreads();
        {
            const float4* src = (const float4*)(W2 + (size_t)jc * DD);
            float4* dst = (float4*)W2s;
            for (int i = tid; i < 64 * DD / 4; i += QBLK) dst[i] = src[i];
        }
        __syncthreads();
        #pragma unroll 4
        for (int j = 0; j < 64; j++) {
            const int jj = jc + j;
            float h = fmaxf(c0 * W1s[jj] + c1 * W1s[HH + jj] +
                            c2 * W1s[2 * HH + jj] + b1s[jj], 0.f);
            const float4* w2row = (const float4*)(W2s + j * DD + d0);
            #pragma unroll
            for (int q4 = 0; q4 < 4; q4++) {
                float4 w = w2row[q4];
                acc[4 * q4 + 0] += h * w.x;
                acc[4 * q4 + 1] += h * w.y;
                acc[4 * q4 + 2] += h * w.z;
                acc[4 * q4 + 3] += h * w.w;
            }
        }
    }

    float psum = 0.f;
    if (p < npts) {
        float4* o = (float4*)(outg + (size_t)p * DD + d0);
        #pragma unroll
        for (int q4 = 0; q4 < 4; q4++) {
            float4 r;
            r.x = acc[4 * q4 + 0] + b2s[d0 + 4 * q4 + 0];
            r.y = acc[4 * q4 + 1] + b2s[d0 + 4 * q4 + 1];
            r.z = acc[4 * q4 + 2] + b2s[d0 + 4 * q4 + 2];
            r.w = acc[4 * q4 + 3] + b2s[d0 + 4 * q4 + 3];
            o[q4] = r;
            psum += (r.x + r.y) + (r.z + r.w);
        }
    }
    // combine the 4 sibling lanes' 16-dim partial sums
    psum += __shfl_xor_sync(0xFFFFFFFFu, psum, 1);
    psum += __shfl_xor_sync(0xFFFFFFFFu, psum, 2);
    if (p < npts && dpart == 0) sumg[p] = psum;
}

// ---------------------------------------------------------------------------
// Stage 2: fused L1-cdist (min-sum identity) + tile-deferred online softmax
// + PV. Per dim: 1 FMNMX (alu) + 1 FADD (fma) — pipes balanced.
// ---------------------------------------------------------------------------
__global__ __launch_bounds__(QBLK, 3) void attn_partial_kernel(
    const float* __restrict__ values)
{
    __shared__ __align__(16) float ks[2][TK * DD];   // 2 x 2 KB
    __shared__ __align__(16) float vs[2][TK * KV];   // 2 x 1 KB
    __shared__ float kss[2][TK];

    const int tid   = threadIdx.x;
    const int b     = blockIdx.y;
    const int m     = blockIdx.x * QBLK + tid;
    const int split = blockIdx.z;
    const int gq    = b * MM + m;

    // query into scalar registers
    float q[DD];
    {
        const float4* qp = (const float4*)(g_query + (size_t)gq * DD);
        #pragma unroll
        for (int i = 0; i < DD / 4; i++) {
            float4 v4 = qp[i];
            q[4 * i + 0] = v4.x; q[4 * i + 1] = v4.y;
            q[4 * i + 2] = v4.z; q[4 * i + 3] = v4.w;
        }
    }
    const float qs = g_qsum[gq];

    float mval = -FLT_MAX;
    float ssum = 0.f;
    u64 acc[KV / 2];
    #pragma unroll
    for (int j = 0; j < KV / 2; j++) acc[j] = 0ULL;

    const int    n0      = split * NSPLIT;
    const float* keyBase = g_key  + (size_t)b * NN * DD + (size_t)n0 * DD;
    const float* valBase = values + (size_t)b * NN * KV + (size_t)n0 * KV;
    const float* ksBase  = g_ksum + (size_t)b * NN + n0;

    // preload tile 0
    ((float4*)ks[0])[tid] = ((const float4*)keyBase)[tid];           // 128 float4
    if (tid < TK * KV / 4)
        ((float4*)vs[0])[tid] = ((const float4*)valBase)[tid];       // 64 float4
    if (tid < TK)
        kss[0][tid] = ksBase[tid];
    __syncthreads();

    const int NT = NSPLIT / TK;   // 8 tiles
    for (int t = 0; t < NT; t++) {
        const int cur = t & 1;
        if (t + 1 < NT) {   // prefetch next tile into the other buffer
            ((float4*)ks[cur ^ 1])[tid] =
                ((const float4*)(keyBase + (size_t)(t + 1) * TK * DD))[tid];
            if (tid < TK * KV / 4)
                ((float4*)vs[cur ^ 1])[tid] =
                    ((const float4*)(valBase + (size_t)(t + 1) * TK * KV))[tid];
            if (tid < TK)
                kss[cur ^ 1][tid] = ksBase[(t + 1) * TK + tid];
        }

        // ---- pass A: L1 via min-sum -> base-2 logits for TK keys ----
        float lg[TK];
        float tm = -FLT_MAX;
        #pragma unroll
        for (int kk = 0; kk < TK; kk++) {
            const float4* kp = (const float4*)(ks[cur] + kk * DD);
            float m0 = 0.f, m1 = 0.f, m2 = 0.f, m3 = 0.f;
            #pragma unroll
            for (int i = 0; i < DD / 4; i++) {
                float4 k4 = kp[i];
                m0 += fminf(k4.x, q[4 * i + 0]);
                m1 += fminf(k4.y, q[4 * i + 1]);
                m2 += fminf(k4.z, q[4 * i + 2]);
                m3 += fminf(k4.w, q[4 * i + 3]);
            }
            float s = fmaf(-2.f, (m0 + m1) + (m2 + m3), kss[cur][kk] + qs);
            float lgv = (NLOG2E_HALF * s) * s;
            lg[kk] = lgv;
            tm = fmaxf(tm, lgv);
        }

        // ---- tile-level branchless rescale ----
        float newm = fmaxf(mval, tm);
        float corr = ex2_(mval - newm);     // -FLT_MAX - finite -> ex2 -> 0
        mval = newm;
        ssum *= corr;
        u64 corrp = pack2_(corr, corr);
        #pragma unroll
        for (int j = 0; j < KV / 2; j++) acc[j] = mul2_(acc[j], corrp);

        // ---- pass B: weights + PV ----
        #pragma unroll
        for (int kk = 0; kk < TK; kk++) {
            float p = ex2_(lg[kk] - mval);
            ssum += p;
            u64 pp = pack2_(p, p);
            const ulonglong2* vp = (const ulonglong2*)(vs[cur] + kk * KV);
            #pragma unroll
            for (int j = 0; j < KV / 4; j++) {
                ulonglong2 v2 = vp[j];
                acc[2 * j + 0] = fma2_(v2.x, pp, acc[2 * j + 0]);
                acc[2 * j + 1] = fma2_(v2.y, pp, acc[2 * j + 1]);
            }
        }
        __syncthreads();
    }

    // write partial: [split][comp][gq], coalesced across tid
    float* base = g_part + (size_t)split * NCOMP * BM + gq;
    base[0]          = mval;
    base[(size_t)BM] = ssum;
    #pragma unroll
    for (int j = 0; j < KV / 2; j++) {
        float lo, hi;
        unpack2_(acc[j], lo, hi);
        base[(size_t)(2 + 2 * j + 0) * BM] = lo;
        base[(size_t)(2 + 2 * j + 1) * BM] = hi;
    }
}

// ---------------------------------------------------------------------------
// Stage 3: merge. One thread per (query, 4 value dims) -> 65536 threads.
// ---------------------------------------------------------------------------
__global__ __launch_bounds__(256) void merge_kernel(float* __restrict__ out)
{
    const int idx  = blockIdx.x * 256 + threadIdx.x;   // < BM * 8
    const int gq   = idx >> 3;
    const int quad = idx & 7;

    float mx = -FLT_MAX;
    #pragma unroll
    for (int s = 0; s < SPLITS; s++)
        mx = fmaxf(mx, g_part[(size_t)s * NCOMP * BM + gq]);

    float tot = 0.f;
    float a0 = 0.f, a1 = 0.f, a2 = 0.f, a3 = 0.f;
    #pragma unroll
    for (int s = 0; s < SPLITS; s++) {
        const float* base = g_part + (size_t)s * NCOMP * BM + gq;
        float w = ex2_(base[0] - mx);
        tot += base[(size_t)BM] * w;
        const float* ab = base + (size_t)(2 + 4 * quad) * BM;
        a0 += ab[0]              * w;
        a1 += ab[(size_t)BM]     * w;
        a2 += ab[(size_t)2 * BM] * w;
        a3 += ab[(size_t)3 * BM] * w;
    }

    float inv = 1.f / tot;
    float4 r = make_float4(a0 * inv, a1 * inv, a2 * inv, a3 * inv);
    *(float4*)(out + (size_t)gq * KV + 4 * quad) = r;
}

// ---------------------------------------------------------------------------
extern "C" void kernel_launch(void* const* d_in, const int* in_sizes, int n_in,
                              void* d_out, int out_size)
{
    const float* coords_f = (const float*)d_in[0];
    const float* values_f = (const float*)d_in[1];
    const float* coords_t = (const float*)d_in[2];
    const float* Wk1 = (const float*)d_in[3];
    const float* bk1 = (const float*)d_in[4];
    const float* Wk2 = (const float*)d_in[5];
    const float* bk2 = (const float*)d_in[6];
    const float* Wq1 = (const float*)d_in[7];
    const float* bq1 = (const float*)d_in[8];
    const float* Wq2 = (const float*)d_in[9];
    const float* bq2 = (const float*)d_in[10];
    float* out = (float*)d_out;

    {
        int npts = BB * NN;                       // 8192
        int blocks = (npts * 4) / QBLK;           // 256
        embed_kernel<<<blocks, QBLK>>>(coords_f, Wk1, bk1, Wk2, bk2, 0, npts);
        embed_kernel<<<blocks, QBLK>>>(coords_t, Wq1, bq1, Wq2, bq2, 1, npts);
    }

    {
        dim3 grid(MM / QBLK, BB, SPLITS);         // (16, 4, 32) = 2048 blocks
        attn_partial_kernel<<<grid, QBLK>>>(values_f);
    }

    merge_kernel<<<(BM * 8) / 256, 256>>>(out);
}